// round 14
// baseline (speedup 1.0000x reference)
#include <cuda_runtime.h>

typedef unsigned long long u64;
typedef unsigned int u32;

#define B 32
#define N 2048
#define C 64
#define R 32
#define K 64

__device__ float g_vals[B * K];
__device__ int   g_idx[B * K];
__device__ u64   g_part[B * 8 * 64];    // per-chunk top-64 sorted lists (8 chunks)

// Monotone key: descending value, ascending index, as one u64 (bigger = first).
__device__ __forceinline__ u64 make_key(float v, int idx) {
    u32 u = __float_as_uint(v);
    u = (u & 0x80000000u) ? ~u : (u | 0x80000000u);   // order-preserving f32->u32
    return ((u64)u << 32) | (u32)(N - 1 - idx);       // low word: smaller idx wins
}

__device__ __forceinline__ void unmake_key(u64 kk, float& v, int& id) {
    id = (N - 1) - (int)(kk & 0xffffffffu);
    u32 hu = (u32)(kk >> 32);
    u32 fb = (hu & 0x80000000u) ? (hu ^ 0x80000000u) : ~hu;
    v = __uint_as_float(fb);
}

// compare-exchange on packed keys; partner differs in lane bit j
__device__ __forceinline__ void cmpx64(u64& k, int j, bool desc) {
    u64 o = __shfl_xor_sync(0xffffffffu, k, j);
    bool keep_big = (((threadIdx.x & 31) & j) == 0) == desc;
    k = ((k > o) == keep_big) ? k : o;
}

// warp-level: sort 64 keys (2 per lane) descending
__device__ __forceinline__ void warp_sort64(u64& k0, u64& k1) {
    const int lane = threadIdx.x & 31;
    #pragma unroll
    for (int k = 2; k <= 32; k <<= 1) {
        #pragma unroll
        for (int j = k >> 1; j >= 1; j >>= 1) {
            cmpx64(k0, j, ((lane)      & k) == 0);
            cmpx64(k1, j, ((lane + 32) & k) == 0);
        }
    }
    if (!(k0 > k1)) { u64 t = k0; k0 = k1; k1 = t; }
    #pragma unroll
    for (int j = 16; j >= 1; j >>= 1) { cmpx64(k0, j, true); cmpx64(k1, j, true); }
}

// warp-level: top-64 of two sorted-desc 64-lists; result sorted-desc in a0/a1
__device__ __forceinline__ void warp_merge64(u64& a0, u64& a1, u64 b0, u64 b1) {
    u64 m0 = __shfl_xor_sync(0xffffffffu, b1, 31);   // B[63-e] for e=lane
    u64 m1 = __shfl_xor_sync(0xffffffffu, b0, 31);   // B[63-e] for e=lane+32
    if (m0 > a0) a0 = m0;
    if (m1 > a1) a1 = m1;
    if (!(a0 > a1)) { u64 t = a0; a0 = a1; a1 = t; }
    #pragma unroll
    for (int j = 16; j >= 1; j >>= 1) { cmpx64(a0, j, true); cmpx64(a1, j, true); }
}

// block-level (256 thr / 8 warps): merge the 8 sorted lists of batch b from
// g_part into the final sorted-desc top-64, returned in warp 0's (f0, f1).
// RACE-FIX: barrier between each round's loads and stores (writer warp w
// overlaps reader warp w/2 on slot w).
__device__ __forceinline__ void block_merge8(int b, u64* sk, u64& f0, u64& f1) {
    const int tid  = threadIdx.x;
    const int lane = tid & 31;
    const int w    = tid >> 5;            // warp 0..7

    sk[w * 64 + lane]      = g_part[(b * 8 + w) * 64 + lane];
    sk[w * 64 + 32 + lane] = g_part[(b * 8 + w) * 64 + 32 + lane];
    __syncthreads();

    #pragma unroll
    for (int t = 0; t < 3; t++) {
        const int nw = 4 >> t;            // 4, 2, 1
        u64 a0 = 0, a1 = 0, b0 = 0, b1 = 0;
        if (w < nw) {
            const int la = 2 * w, lb = 2 * w + 1;
            a0 = sk[la * 64 + lane];
            a1 = sk[la * 64 + 32 + lane];
            b0 = sk[lb * 64 + lane];
            b1 = sk[lb * 64 + 32 + lane];
        }
        __syncthreads();                  // all reads done before any write
        if (w < nw) {
            warp_merge64(a0, a1, b0, b1);
            if (t < 2) {
                sk[w * 64 + lane]      = a0;
                sk[w * 64 + 32 + lane] = a1;
            } else { f0 = a0; f1 = a1; }
        }
        __syncthreads();                  // writes visible before next reads
    }
}

// ---------------------------------------------------------------------------
// Stage 1 (side stream, head of critical path): grid (8, B) x 128 thr.
// Block sorts ONE 256-elem chunk -> top-64 sorted list into g_part.
// ---------------------------------------------------------------------------
__global__ __launch_bounds__(128)
void topk_part(const float* __restrict__ acc) {
    __shared__ u64 sk[256];
    const int b    = blockIdx.y;
    const int c    = blockIdx.x;          // chunk 0..7
    const int tid  = threadIdx.x;
    const int lane = tid & 31;
    const int w    = tid >> 5;            // warp 0..3

    const float* row = acc + b * N + c * 256;
    const int base = c * 256 + w * 64;
    u64 k0 = make_key(row[w * 64 + lane],      base + lane);
    u64 k1 = make_key(row[w * 64 + 32 + lane], base + 32 + lane);
    warp_sort64(k0, k1);

    sk[w * 64 + lane]      = k0;
    sk[w * 64 + 32 + lane] = k1;
    __syncthreads();

    // 2 merge rounds: 4 lists -> 1 (same race fix: load/barrier/store/barrier)
    u64 f0 = 0, f1 = 0;
    #pragma unroll
    for (int t = 0; t < 2; t++) {
        const int nw = 2 >> t;            // 2, 1
        u64 a0 = 0, a1 = 0, b0 = 0, b1 = 0;
        if (w < nw) {
            const int la = 2 * w, lb = 2 * w + 1;
            a0 = sk[la * 64 + lane];
            a1 = sk[la * 64 + 32 + lane];
            b0 = sk[lb * 64 + lane];
            b1 = sk[lb * 64 + 32 + lane];
        }
        __syncthreads();
        if (w < nw) {
            warp_merge64(a0, a1, b0, b1);
            if (t < 1) {
                sk[w * 64 + lane]      = a0;
                sk[w * 64 + 32 + lane] = a1;
            } else { f0 = a0; f1 = a1; }
        }
        __syncthreads();
    }

    if (w == 0) {
        g_part[(b * 8 + c) * 64 + lane]      = f0;
        g_part[(b * 8 + c) * 64 + 32 + lane] = f1;
    }
}

// ---------------------------------------------------------------------------
// merge_emit (side stream, hidden under M): grid B x 256. Final merge, emit
// topk_vals / topk_idx outputs and g_vals/g_idx for frob.
// ---------------------------------------------------------------------------
__global__ __launch_bounds__(256)
void merge_emit(float* __restrict__ out) {
    __shared__ u64 sk[512];
    const int b = blockIdx.x;
    u64 f0 = 0, f1 = 0;
    block_merge8(b, sk, f0, f1);

    if ((threadIdx.x >> 5) == 0) {
        const int lane = threadIdx.x & 31;
        #pragma unroll
        for (int h = 0; h < 2; h++) {
            u64 kk = h ? f1 : f0;
            int pos = lane + h * 32;
            float v; int id;
            unmake_key(kk, v, id);
            out[b * K + pos]         = v;           // topk_vals
            out[B * K + b * K + pos] = (float)id;   // topk_idx
            g_vals[b * K + pos] = v;
            g_idx [b * K + pos] = id;
        }
    }
}

// ---------------------------------------------------------------------------
// frob (side stream, after merge_emit, concurrent with M).
// ---------------------------------------------------------------------------
__global__ __launch_bounds__(32)
void frob_kernel(const float* __restrict__ U, float* __restrict__ out) {
    const int c = blockIdx.x;
    const int b = blockIdx.y;
    const int r = threadIdx.x;

    float v0 = g_vals[b * K + r];
    float v1 = g_vals[b * K + 32 + r];
    int   i0 = g_idx [b * K + r];
    int   i1 = g_idx [b * K + 32 + r];

    const float* Uc = U + (size_t)c * N * R;
    float au = 0.0f;
    #pragma unroll
    for (int k = 0; k < 32; k++) {
        float vk = __shfl_sync(0xffffffffu, v0, k);
        int   ik = __shfl_sync(0xffffffffu, i0, k);
        au = fmaf(vk, __ldg(Uc + (size_t)ik * R + r), au);
    }
    #pragma unroll
    for (int k = 0; k < 32; k++) {
        float vk = __shfl_sync(0xffffffffu, v1, k);
        int   ik = __shfl_sync(0xffffffffu, i1, k);
        au = fmaf(vk, __ldg(Uc + (size_t)ik * R + r), au);
    }

    float sq = au * au;
    #pragma unroll
    for (int o = 16; o > 0; o >>= 1)
        sq += __shfl_xor_sync(0xffffffffu, sq, o);
    if (r == 0) out[2 * B * K + b * C + c] = sq / (float)(K * R);
}

// ---------------------------------------------------------------------------
// M_kernel (stream 0, waits only on topk_part): each block merges the 8 lists
// itself in its prologue (hidden under the store stream), builds s_pv locally,
// then runs the PROVEN store loop unchanged.
// ---------------------------------------------------------------------------
__global__ __launch_bounds__(256)
void M_kernel(float* __restrict__ outM) {
    __shared__ float s_pv[N];             // 8 KB
    __shared__ u64   sk[512];             // 4 KB merge scratch
    const int b    = blockIdx.y;
    const int tile = blockIdx.x;
    const int tid  = threadIdx.x;

    // zero s_pv (no dependence)
    float4* s4f = reinterpret_cast<float4*>(s_pv);
    #pragma unroll
    for (int q = 0; q < 2; q++) s4f[tid + q * 256] = make_float4(0.f, 0.f, 0.f, 0.f);

    // local merge of the 8 sorted lists -> top-64 in warp 0 regs
    u64 f0 = 0, f1 = 0;
    block_merge8(b, sk, f0, f1);

    // warp 0 scatters top-64 into s_pv
    if ((tid >> 5) == 0) {
        const int lane = tid & 31;
        #pragma unroll
        for (int h = 0; h < 2; h++) {
            float v; int id;
            unmake_key(h ? f1 : f0, v, id);
            s_pv[id] = v;
        }
    }
    __syncthreads();

    // ---- proven store loop (R2, 76.8us @ 78.4% DRAM) ----
    float4* out4 = reinterpret_cast<float4*>(outM);
    #pragma unroll
    for (int ir = 0; ir < 16; ir++) {
        const int i = tile * 16 + ir;
        const float pvi = s_pv[i];
        const size_t base = ((size_t)b * N + i) * (N / 4);
        #pragma unroll
        for (int jj = 0; jj < 2; jj++) {
            const int j4 = tid + jj * 256;
            float4 v = s4f[j4];
            float4 o = make_float4(pvi * v.x, pvi * v.y, pvi * v.z, pvi * v.w);
            __stcs(&out4[base + j4], o);
        }
    }
}

// Side stream + events (host resources only — no device memory).
static cudaStream_t g_s_side;
static cudaEvent_t  g_ev_fork, g_ev_part, g_ev_side;
struct _StreamInit {
    _StreamInit() {
        cudaStreamCreateWithFlags(&g_s_side, cudaStreamNonBlocking);
        cudaEventCreateWithFlags(&g_ev_fork, cudaEventDisableTiming);
        cudaEventCreateWithFlags(&g_ev_part, cudaEventDisableTiming);
        cudaEventCreateWithFlags(&g_ev_side, cudaEventDisableTiming);
    }
};
static _StreamInit g_stream_init;

extern "C" void kernel_launch(void* const* d_in, const int* in_sizes, int n_in,
                              void* d_out, int out_size) {
    const float* acc = (const float*)d_in[0];   // [B, N] float32
    const float* U   = (const float*)d_in[1];   // [C, N, R] float32
    float* out  = (float*)d_out;
    float* outM = out + 3 * B * K;

    // Legal fork: side stream joins capture via event wait on stream 0.
    cudaEventRecord(g_ev_fork, (cudaStream_t)0);
    cudaStreamWaitEvent(g_s_side, g_ev_fork, 0);

    // Side stream: part -> (record) -> merge_emit -> frob.
    topk_part<<<dim3(8, B), 128, 0, g_s_side>>>(acc);
    cudaEventRecord(g_ev_part, g_s_side);
    merge_emit<<<B, 256, 0, g_s_side>>>(out);
    frob_kernel<<<dim3(C, B), 32, 0, g_s_side>>>(U, out);
    cudaEventRecord(g_ev_side, g_s_side);

    // Stream 0: M waits only on topk_part (g_part ready), merges in-block.
    cudaStreamWaitEvent((cudaStream_t)0, g_ev_part, 0);
    M_kernel<<<dim3(N / 16, B), 256>>>(outM);

    // Join side stream.
    cudaStreamWaitEvent((cudaStream_t)0, g_ev_side, 0);
}

// round 15
// speedup vs baseline: 1.0155x; 1.0155x over previous
#include <cuda_runtime.h>

typedef unsigned long long u64;
typedef unsigned int u32;

#define B 32
#define N 2048
#define C 64
#define R 32
#define K 64

__device__ float g_vals[B * K];
__device__ int   g_idx[B * K];
__device__ u64   g_part[B * 8 * 64];    // per-chunk top-64 sorted lists (8 chunks)

// Monotone key: descending value, ascending index, as one u64 (bigger = first).
__device__ __forceinline__ u64 make_key(float v, int idx) {
    u32 u = __float_as_uint(v);
    u = (u & 0x80000000u) ? ~u : (u | 0x80000000u);   // order-preserving f32->u32
    return ((u64)u << 32) | (u32)(N - 1 - idx);       // low word: smaller idx wins
}

__device__ __forceinline__ void unmake_key(u64 kk, float& v, int& id) {
    id = (N - 1) - (int)(kk & 0xffffffffu);
    u32 hu = (u32)(kk >> 32);
    u32 fb = (hu & 0x80000000u) ? (hu ^ 0x80000000u) : ~hu;
    v = __uint_as_float(fb);
}

// compare-exchange on packed keys; partner differs in lane bit j
__device__ __forceinline__ void cmpx64(u64& k, int j, bool desc) {
    u64 o = __shfl_xor_sync(0xffffffffu, k, j);
    bool keep_big = (((threadIdx.x & 31) & j) == 0) == desc;
    k = ((k > o) == keep_big) ? k : o;
}

// warp-level: sort 64 keys (2 per lane) descending
__device__ __forceinline__ void warp_sort64(u64& k0, u64& k1) {
    const int lane = threadIdx.x & 31;
    #pragma unroll
    for (int k = 2; k <= 32; k <<= 1) {
        #pragma unroll
        for (int j = k >> 1; j >= 1; j >>= 1) {
            cmpx64(k0, j, ((lane)      & k) == 0);
            cmpx64(k1, j, ((lane + 32) & k) == 0);
        }
    }
    if (!(k0 > k1)) { u64 t = k0; k0 = k1; k1 = t; }
    #pragma unroll
    for (int j = 16; j >= 1; j >>= 1) { cmpx64(k0, j, true); cmpx64(k1, j, true); }
}

// warp-level: top-64 of two sorted-desc 64-lists; result sorted-desc in a0/a1
__device__ __forceinline__ void warp_merge64(u64& a0, u64& a1, u64 b0, u64 b1) {
    u64 m0 = __shfl_xor_sync(0xffffffffu, b1, 31);   // B[63-e] for e=lane
    u64 m1 = __shfl_xor_sync(0xffffffffu, b0, 31);   // B[63-e] for e=lane+32
    if (m0 > a0) a0 = m0;
    if (m1 > a1) a1 = m1;
    if (!(a0 > a1)) { u64 t = a0; a0 = a1; a1 = t; }
    #pragma unroll
    for (int j = 16; j >= 1; j >>= 1) { cmpx64(a0, j, true); cmpx64(a1, j, true); }
}

// block-level (256 thr / 8 warps): merge the 8 sorted lists of batch b from
// g_part into the final sorted-desc top-64, returned in warp 0's (f0, f1).
// Race-safe: barrier between each round's loads and stores.
__device__ __forceinline__ void block_merge8(int b, u64* sk, u64& f0, u64& f1) {
    const int tid  = threadIdx.x;
    const int lane = tid & 31;
    const int w    = tid >> 5;            // warp 0..7

    sk[w * 64 + lane]      = g_part[(b * 8 + w) * 64 + lane];
    sk[w * 64 + 32 + lane] = g_part[(b * 8 + w) * 64 + 32 + lane];
    __syncthreads();

    #pragma unroll
    for (int t = 0; t < 3; t++) {
        const int nw = 4 >> t;            // 4, 2, 1
        u64 a0 = 0, a1 = 0, b0 = 0, b1 = 0;
        if (w < nw) {
            const int la = 2 * w, lb = 2 * w + 1;
            a0 = sk[la * 64 + lane];
            a1 = sk[la * 64 + 32 + lane];
            b0 = sk[lb * 64 + lane];
            b1 = sk[lb * 64 + 32 + lane];
        }
        __syncthreads();                  // all reads done before any write
        if (w < nw) {
            warp_merge64(a0, a1, b0, b1);
            if (t < 2) {
                sk[w * 64 + lane]      = a0;
                sk[w * 64 + 32 + lane] = a1;
            } else { f0 = a0; f1 = a1; }
        }
        __syncthreads();                  // writes visible before next reads
    }
}

// ---------------------------------------------------------------------------
// Stage 1 (stream 0, head of critical path): grid (8, B) x 128 thr.
// Block sorts ONE 256-elem chunk -> top-64 sorted list into g_part.
// Ends with launch_dependents for the PDL-chained M_kernel.
// ---------------------------------------------------------------------------
__global__ __launch_bounds__(128)
void topk_part(const float* __restrict__ acc) {
    __shared__ u64 sk[256];
    const int b    = blockIdx.y;
    const int c    = blockIdx.x;          // chunk 0..7
    const int tid  = threadIdx.x;
    const int lane = tid & 31;
    const int w    = tid >> 5;            // warp 0..3

    const float* row = acc + b * N + c * 256;
    const int base = c * 256 + w * 64;
    u64 k0 = make_key(row[w * 64 + lane],      base + lane);
    u64 k1 = make_key(row[w * 64 + 32 + lane], base + 32 + lane);
    warp_sort64(k0, k1);

    sk[w * 64 + lane]      = k0;
    sk[w * 64 + 32 + lane] = k1;
    __syncthreads();

    // 2 merge rounds: 4 lists -> 1 (race-safe load/barrier/store/barrier)
    u64 f0 = 0, f1 = 0;
    #pragma unroll
    for (int t = 0; t < 2; t++) {
        const int nw = 2 >> t;            // 2, 1
        u64 a0 = 0, a1 = 0, b0 = 0, b1 = 0;
        if (w < nw) {
            const int la = 2 * w, lb = 2 * w + 1;
            a0 = sk[la * 64 + lane];
            a1 = sk[la * 64 + 32 + lane];
            b0 = sk[lb * 64 + lane];
            b1 = sk[lb * 64 + 32 + lane];
        }
        __syncthreads();
        if (w < nw) {
            warp_merge64(a0, a1, b0, b1);
            if (t < 1) {
                sk[w * 64 + lane]      = a0;
                sk[w * 64 + 32 + lane] = a1;
            } else { f0 = a0; f1 = a1; }
        }
        __syncthreads();
    }

    if (w == 0) {
        g_part[(b * 8 + c) * 64 + lane]      = f0;
        g_part[(b * 8 + c) * 64 + 32 + lane] = f1;
    }
    asm volatile("griddepcontrol.launch_dependents;");
}

// ---------------------------------------------------------------------------
// merge_emit (side stream, hidden under M): grid B x 256. Final merge, emit
// topk_vals / topk_idx outputs and g_vals/g_idx for frob.
// ---------------------------------------------------------------------------
__global__ __launch_bounds__(256)
void merge_emit(float* __restrict__ out) {
    __shared__ u64 sk[512];
    const int b = blockIdx.x;
    u64 f0 = 0, f1 = 0;
    block_merge8(b, sk, f0, f1);

    if ((threadIdx.x >> 5) == 0) {
        const int lane = threadIdx.x & 31;
        #pragma unroll
        for (int h = 0; h < 2; h++) {
            u64 kk = h ? f1 : f0;
            int pos = lane + h * 32;
            float v; int id;
            unmake_key(kk, v, id);
            out[b * K + pos]         = v;           // topk_vals
            out[B * K + b * K + pos] = (float)id;   // topk_idx
            g_vals[b * K + pos] = v;
            g_idx [b * K + pos] = id;
        }
    }
}

// ---------------------------------------------------------------------------
// frob (side stream, after merge_emit, concurrent with M).
// ---------------------------------------------------------------------------
__global__ __launch_bounds__(32)
void frob_kernel(const float* __restrict__ U, float* __restrict__ out) {
    const int c = blockIdx.x;
    const int b = blockIdx.y;
    const int r = threadIdx.x;

    float v0 = g_vals[b * K + r];
    float v1 = g_vals[b * K + 32 + r];
    int   i0 = g_idx [b * K + r];
    int   i1 = g_idx [b * K + 32 + r];

    const float* Uc = U + (size_t)c * N * R;
    float au = 0.0f;
    #pragma unroll
    for (int k = 0; k < 32; k++) {
        float vk = __shfl_sync(0xffffffffu, v0, k);
        int   ik = __shfl_sync(0xffffffffu, i0, k);
        au = fmaf(vk, __ldg(Uc + (size_t)ik * R + r), au);
    }
    #pragma unroll
    for (int k = 0; k < 32; k++) {
        float vk = __shfl_sync(0xffffffffu, v1, k);
        int   ik = __shfl_sync(0xffffffffu, i1, k);
        au = fmaf(vk, __ldg(Uc + (size_t)ik * R + r), au);
    }

    float sq = au * au;
    #pragma unroll
    for (int o = 16; o > 0; o >>= 1)
        sq += __shfl_xor_sync(0xffffffffu, sq, o);
    if (r == 0) out[2 * B * K + b * C + c] = sq / (float)(K * R);
}

// ---------------------------------------------------------------------------
// M_kernel (stream 0, PDL on topk_part): zero s_pv first (no dependence),
// then wait, merge the 8 lists in-block (hidden under store stream), build
// s_pv, and run the PROVEN store loop unchanged.
// ---------------------------------------------------------------------------
__global__ __launch_bounds__(256)
void M_kernel(float* __restrict__ outM) {
    __shared__ float s_pv[N];             // 8 KB
    __shared__ u64   sk[512];             // 4 KB merge scratch
    const int b    = blockIdx.y;
    const int tile = blockIdx.x;
    const int tid  = threadIdx.x;

    // zero s_pv before the PDL wait (independent work overlaps topk_part tail)
    float4* s4f = reinterpret_cast<float4*>(s_pv);
    #pragma unroll
    for (int q = 0; q < 2; q++) s4f[tid + q * 256] = make_float4(0.f, 0.f, 0.f, 0.f);

    // PDL: g_part must be ready.
    asm volatile("griddepcontrol.wait;" ::: "memory");

    // local merge of the 8 sorted lists -> top-64 in warp 0 regs
    u64 f0 = 0, f1 = 0;
    block_merge8(b, sk, f0, f1);

    // warp 0 scatters top-64 into s_pv
    if ((tid >> 5) == 0) {
        const int lane = tid & 31;
        #pragma unroll
        for (int h = 0; h < 2; h++) {
            float v; int id;
            unmake_key(h ? f1 : f0, v, id);
            s_pv[id] = v;
        }
    }
    __syncthreads();

    // ---- proven store loop (76.5us @ 78.7% DRAM) ----
    float4* out4 = reinterpret_cast<float4*>(outM);
    #pragma unroll
    for (int ir = 0; ir < 16; ir++) {
        const int i = tile * 16 + ir;
        const float pvi = s_pv[i];
        const size_t base = ((size_t)b * N + i) * (N / 4);
        #pragma unroll
        for (int jj = 0; jj < 2; jj++) {
            const int j4 = tid + jj * 256;
            float4 v = s4f[j4];
            float4 o = make_float4(pvi * v.x, pvi * v.y, pvi * v.z, pvi * v.w);
            __stcs(&out4[base + j4], o);
        }
    }
}

// Side stream + events (host resources only — no device memory).
static cudaStream_t g_s_side;
static cudaEvent_t  g_ev_part, g_ev_side;
struct _StreamInit {
    _StreamInit() {
        cudaStreamCreateWithFlags(&g_s_side, cudaStreamNonBlocking);
        cudaEventCreateWithFlags(&g_ev_part, cudaEventDisableTiming);
        cudaEventCreateWithFlags(&g_ev_side, cudaEventDisableTiming);
    }
};
static _StreamInit g_stream_init;

static void launch_pdl(void* fn, dim3 grid, dim3 block, void** args) {
    cudaLaunchConfig_t cfg = {};
    cfg.gridDim  = grid;
    cfg.blockDim = block;
    cfg.dynamicSmemBytes = 0;
    cfg.stream = (cudaStream_t)0;
    cudaLaunchAttribute attr[1];
    attr[0].id = cudaLaunchAttributeProgrammaticStreamSerialization;
    attr[0].val.programmaticStreamSerializationAllowed = 1;
    cfg.attrs = attr;
    cfg.numAttrs = 1;
    cudaLaunchKernelExC(&cfg, fn, args);
}

extern "C" void kernel_launch(void* const* d_in, const int* in_sizes, int n_in,
                              void* d_out, int out_size) {
    const float* acc = (const float*)d_in[0];   // [B, N] float32
    const float* U   = (const float*)d_in[1];   // [C, N, R] float32
    float* out  = (float*)d_out;
    float* outM = out + 3 * B * K;

    // Stream 0: topk_part heads the critical path (256 blocks, ~1.5-2us).
    topk_part<<<dim3(8, B), 128>>>(acc);

    // Fork side stream after topk_part: merge_emit + frob hidden under M.
    cudaEventRecord(g_ev_part, (cudaStream_t)0);
    cudaStreamWaitEvent(g_s_side, g_ev_part, 0);
    merge_emit<<<B, 256, 0, g_s_side>>>(out);
    frob_kernel<<<dim3(C, B), 32, 0, g_s_side>>>(U, out);
    cudaEventRecord(g_ev_side, g_s_side);

    // Stream 0: M via same-stream PDL on topk_part (R7-proven cheap edge).
    {
        void* args[] = { (void*)&outM };
        launch_pdl((void*)M_kernel, dim3(N / 16, B), dim3(256), args);
    }

    // Join side stream.
    cudaStreamWaitEvent((cudaStream_t)0, g_ev_side, 0);
}